// round 3
// baseline (speedup 1.0000x reference)
#include <cuda_runtime.h>
#include <math.h>
#include <stdint.h>

typedef unsigned long long ull;

// ---------------------------------------------------------------- constants
constexpr int BATCH = 64;
constexpr int SEQ   = 512;
constexpr int WIDTH = 256;   // hidden width
constexpr int EMBED = 512;   // 2*WIDTH
constexpr int ROWS  = BATCH * SEQ;   // 32768 GEMM rows

// ---------------------------------------------------------------- scratch
// bufA: xw1, later reused for xw2. bufB: h1 sequence.
__device__ float g_bufA[BATCH * SEQ * WIDTH];
__device__ float g_bufB[BATCH * SEQ * WIDTH];

// ---------------------------------------------------------------- f32x2 helpers
__device__ __forceinline__ ull pk2(float lo, float hi) {
    ull r; asm("mov.b64 %0,{%1,%2};" : "=l"(r) : "f"(lo), "f"(hi)); return r;
}
__device__ __forceinline__ void up2(ull v, float& lo, float& hi) {
    asm("mov.b64 {%0,%1},%2;" : "=f"(lo), "=f"(hi) : "l"(v));
}
__device__ __forceinline__ ull ffma2(ull a, ull b, ull c) {
    ull d; asm("fma.rn.f32x2 %0,%1,%2,%3;" : "=l"(d) : "l"(a), "l"(b), "l"(c)); return d;
}

// ============================================================================
// GEMM: C[R, 256] = A[R, K] @ Wm[K, 256] + bias
// GATHER: A row r is emb[tokens[r]] (K = EMBED); else A row r is A + r*K.
// CTA tile 128x128, 512 threads, per-thread 8 rows x 4 cols, f32x2 FMAs.
// ============================================================================
template<bool GATHER>
__global__ void __launch_bounds__(512, 1)
gemm_kernel(const int* __restrict__ tokens, const float* __restrict__ A,
            const float* __restrict__ Wm, const float* __restrict__ bias,
            float* __restrict__ C, int K)
{
    __shared__ ull   ATu[16][128];   // A tile transposed, each value pre-duplicated (a,a)
    __shared__ float Bs[16][128];    // B tile [k][n]

    const int tid = threadIdx.x;
    const int r0  = blockIdx.x * 128;
    const int n0  = blockIdx.y * 128;

    // --- A loader: 128 rows x 16 k, one float4 per thread ---
    const int lrow = tid >> 2;          // 0..127
    const int lkq  = (tid & 3) * 4;     // 0,4,8,12
    const float* arow;
    if (GATHER) arow = A + (size_t)tokens[r0 + lrow] * (size_t)K;
    else        arow = A + (size_t)(r0 + lrow) * (size_t)K;

    // --- B loader: 16 k x 128 n, one float4 per thread ---
    const int bn = (tid & 31) * 4;
    const int bk = tid >> 5;            // 0..15

    // --- compute mapping: 16 row-groups x 32 col-groups ---
    const int ty = tid >> 5;            // 0..15
    const int tx = tid & 31;            // 0..31
    const int cm = ty * 8;
    const int cn = tx * 4;

    ull acc[8][2];
    #pragma unroll
    for (int r = 0; r < 8; r++) { acc[r][0] = 0ull; acc[r][1] = 0ull; }

    #pragma unroll 1
    for (int k0 = 0; k0 < K; k0 += 16) {
        float4 a4 = *(const float4*)(arow + k0 + lkq);
        float4 b4 = *(const float4*)(Wm + (size_t)(k0 + bk) * WIDTH + n0 + bn);
        __syncthreads();
        ATu[lkq + 0][lrow] = pk2(a4.x, a4.x);
        ATu[lkq + 1][lrow] = pk2(a4.y, a4.y);
        ATu[lkq + 2][lrow] = pk2(a4.z, a4.z);
        ATu[lkq + 3][lrow] = pk2(a4.w, a4.w);
        *(float4*)&Bs[bk][bn] = b4;
        __syncthreads();

        #pragma unroll
        for (int kk = 0; kk < 16; kk++) {
            ulonglong2 bv = *(const ulonglong2*)&Bs[kk][cn];  // (n0..n1),(n2..n3)
            #pragma unroll
            for (int r = 0; r < 8; r++) {
                ull ad = ATu[kk][cm + r];                     // broadcast
                acc[r][0] = ffma2(ad, bv.x, acc[r][0]);
                acc[r][1] = ffma2(ad, bv.y, acc[r][1]);
            }
        }
    }

    const float bv0 = bias[n0 + cn + 0];
    const float bv1 = bias[n0 + cn + 1];
    const float bv2 = bias[n0 + cn + 2];
    const float bv3 = bias[n0 + cn + 3];
    #pragma unroll
    for (int r = 0; r < 8; r++) {
        float c0, c1, c2, c3;
        up2(acc[r][0], c0, c1);
        up2(acc[r][1], c2, c3);
        float4 o = make_float4(c0 + bv0, c1 + bv1, c2 + bv2, c3 + bv3);
        *(float4*)&C[(size_t)(r0 + cm + r) * WIDTH + n0 + cn] = o;
    }
}

// ============================================================================
// RNN scan: one CTA per batch row, 256 threads (thread j owns output column j).
// h_new[j] = tanh(xw[t][j] + sum_k h[k]*U[k][j])
// U rows [0,KREG) live in registers (packed f32x2 pairs along k),
// U rows [KREG,256) live in SMEM as packed pairs.
// ============================================================================
constexpr int KREG = 192;
constexpr int KSM  = WIDTH - KREG;  // 64
constexpr int MREG = KREG / 2;      // 96 b64 regs per thread
constexpr int MSM  = KSM / 2;       // 32 pair-rows in smem

constexpr size_t RNN_SMEM = (size_t)MSM * WIDTH * 8   // usm
                          + 2 * WIDTH * 4             // h ping-pong
                          + 2 * WIDTH * 4;            // reduction scratch

template<bool WRITE_SEQ, bool FINAL>
__global__ void __launch_bounds__(256, 1)
rnn_kernel(const float* __restrict__ xw, const float* __restrict__ U,
           float* __restrict__ hs, const float* __restrict__ Wd,
           const float* __restrict__ bd, float* __restrict__ out)
{
    extern __shared__ unsigned char smraw[];
    ull*   usm = (ull*)smraw;                                 // [MSM][WIDTH]
    float* hb  = (float*)(smraw + (size_t)MSM * WIDTH * 8);   // [2][WIDTH]
    float* red = hb + 2 * WIDTH;                              // [2][WIDTH]

    const int b = blockIdx.x;
    const int j = threadIdx.x;

    // load U columns: registers (rows 0..KREG-1, packed pairs along k)
    ull ureg[MREG];
    #pragma unroll
    for (int m = 0; m < MREG; m++)
        ureg[m] = pk2(U[(2 * m) * WIDTH + j], U[(2 * m + 1) * WIDTH + j]);
    // smem part (rows KREG..255)
    #pragma unroll
    for (int m = 0; m < MSM; m++)
        usm[m * WIDTH + j] = pk2(U[(KREG + 2 * m) * WIDTH + j],
                                 U[(KREG + 2 * m + 1) * WIDTH + j]);

    hb[j] = 0.0f;
    hb[WIDTH + j] = 0.0f;
    __syncthreads();

    const float* xb = xw + (size_t)b * SEQ * WIDTH + j;
    float xt_next = xb[0];
    int cur = 0;
    float hn = 0.0f;

    #pragma unroll 1
    for (int t = 0; t < SEQ; t++) {
        const float xt = xt_next;
        if (t + 1 < SEQ) xt_next = xb[(size_t)(t + 1) * WIDTH];

        const ull* hp = (const ull*)(hb + cur * WIDTH);  // 128 packed h pairs
        ull a0 = 0ull, a1 = 0ull, a2 = 0ull, a3 = 0ull;

        #pragma unroll
        for (int m = 0; m < MREG; m += 4) {
            ulonglong2 h01 = *(const ulonglong2*)(hp + m);
            ulonglong2 h23 = *(const ulonglong2*)(hp + m + 2);
            a0 = ffma2(h01.x, ureg[m + 0], a0);
            a1 = ffma2(h01.y, ureg[m + 1], a1);
            a2 = ffma2(h23.x, ureg[m + 2], a2);
            a3 = ffma2(h23.y, ureg[m + 3], a3);
        }
        #pragma unroll
        for (int m = 0; m < MSM; m += 4) {
            ulonglong2 h01 = *(const ulonglong2*)(hp + MREG + m);
            ulonglong2 h23 = *(const ulonglong2*)(hp + MREG + m + 2);
            a0 = ffma2(h01.x, usm[(m + 0) * WIDTH + j], a0);
            a1 = ffma2(h01.y, usm[(m + 1) * WIDTH + j], a1);
            a2 = ffma2(h23.x, usm[(m + 2) * WIDTH + j], a2);
            a3 = ffma2(h23.y, usm[(m + 3) * WIDTH + j], a3);
        }

        float s0, s1, s2, s3, s4, s5, s6, s7;
        up2(a0, s0, s1); up2(a1, s2, s3); up2(a2, s4, s5); up2(a3, s6, s7);
        const float pre = xt + (((s0 + s1) + (s2 + s3)) + ((s4 + s5) + (s6 + s7)));
        hn = tanhf(pre);

        if (WRITE_SEQ)
            hs[(size_t)b * SEQ * WIDTH + (size_t)t * WIDTH + j] = hn;

        hb[(cur ^ 1) * WIDTH + j] = hn;
        __syncthreads();
        cur ^= 1;
    }

    if (FINAL) {
        // logits[c] = bd[c] + sum_j h_last[j] * Wd[j][c]; then softmax over 2
        red[j]         = hn * Wd[j * 2 + 0];
        red[WIDTH + j] = hn * Wd[j * 2 + 1];
        __syncthreads();
        #pragma unroll
        for (int s = 128; s > 0; s >>= 1) {
            if (j < s) {
                red[j]         += red[j + s];
                red[WIDTH + j] += red[WIDTH + j + s];
            }
            __syncthreads();
        }
        if (j == 0) {
            const float l0 = red[0] + bd[0];
            const float l1 = red[WIDTH] + bd[1];
            const float mx = fmaxf(l0, l1);
            const float e0 = expf(l0 - mx);
            const float e1 = expf(l1 - mx);
            const float inv = 1.0f / (e0 + e1);
            out[b * 2 + 0] = e0 * inv;
            out[b * 2 + 1] = e1 * inv;
        }
    }
}

// ============================================================================
// launcher
// ============================================================================
extern "C" void kernel_launch(void* const* d_in, const int* in_sizes, int n_in,
                              void* d_out, int out_size)
{
    const int*   tokens = (const int*)  d_in[0];
    const float* emb    = (const float*)d_in[1];
    const float* W1     = (const float*)d_in[2];
    const float* U1     = (const float*)d_in[3];
    const float* b1     = (const float*)d_in[4];
    const float* W2     = (const float*)d_in[5];
    const float* U2     = (const float*)d_in[6];
    const float* b2     = (const float*)d_in[7];
    const float* Wd     = (const float*)d_in[8];
    const float* bd     = (const float*)d_in[9];
    float* out = (float*)d_out;

    float* bufA; cudaGetSymbolAddress((void**)&bufA, g_bufA);
    float* bufB; cudaGetSymbolAddress((void**)&bufB, g_bufB);

    // opt-in to >48KB dynamic smem for the RNN kernels (idempotent, capture-safe)
    cudaFuncSetAttribute(rnn_kernel<true, false>,
                         cudaFuncAttributeMaxDynamicSharedMemorySize, (int)RNN_SMEM);
    cudaFuncSetAttribute(rnn_kernel<false, true>,
                         cudaFuncAttributeMaxDynamicSharedMemorySize, (int)RNN_SMEM);

    dim3 ggrid(ROWS / 128, WIDTH / 128);   // (256, 2)

    // 1) xw1 = emb[tokens] @ W1 + b1  -> bufA
    gemm_kernel<true><<<ggrid, 512>>>(tokens, emb, W1, b1, bufA, EMBED);

    // 2) RNN1 scan over bufA with U1 -> h1 sequence in bufB
    rnn_kernel<true, false><<<BATCH, WIDTH, RNN_SMEM>>>(bufA, U1, bufB,
                                                        nullptr, nullptr, nullptr);

    // 3) xw2 = h1 @ W2 + b2 -> bufA (xw1 dead, reuse)
    gemm_kernel<false><<<ggrid, 512>>>(nullptr, bufB, W2, b2, bufA, WIDTH);

    // 4) RNN2 scan over bufA with U2, fused dense + softmax -> out
    rnn_kernel<false, true><<<BATCH, WIDTH, RNN_SMEM>>>(bufA, U2, nullptr,
                                                        Wd, bd, out);

    (void)in_sizes; (void)n_in; (void)out_size;
}

// round 4
// speedup vs baseline: 1.1596x; 1.1596x over previous
#include <cuda_runtime.h>
#include <math.h>
#include <stdint.h>

typedef unsigned long long ull;

// ---------------------------------------------------------------- constants
constexpr int BATCH = 64;
constexpr int SEQ   = 512;
constexpr int WIDTH = 256;   // hidden width
constexpr int EMBED = 512;   // 2*WIDTH
constexpr int ROWS  = BATCH * SEQ;   // 32768 GEMM rows

// ---------------------------------------------------------------- scratch
__device__ float g_bufA[BATCH * SEQ * WIDTH];
__device__ float g_bufB[BATCH * SEQ * WIDTH];

// ---------------------------------------------------------------- f32x2 helpers
__device__ __forceinline__ ull pk2(float lo, float hi) {
    ull r; asm("mov.b64 %0,{%1,%2};" : "=l"(r) : "f"(lo), "f"(hi)); return r;
}
__device__ __forceinline__ void up2(ull v, float& lo, float& hi) {
    asm("mov.b64 {%0,%1},%2;" : "=f"(lo), "=f"(hi) : "l"(v));
}
__device__ __forceinline__ ull ffma2(ull a, ull b, ull c) {
    ull d; asm("fma.rn.f32x2 %0,%1,%2,%3;" : "=l"(d) : "l"(a), "l"(b), "l"(c)); return d;
}
__device__ __forceinline__ uint32_t smem_u32(const void* p) {
    uint32_t a;
    asm("{ .reg .u64 t; cvta.to.shared.u64 t, %1; cvt.u32.u64 %0, t; }"
        : "=r"(a) : "l"(p));
    return a;
}

// ============================================================================
// GEMM: C[R, 256] = A[R, K] @ Wm[K, 256] + bias   (unchanged from R2)
// ============================================================================
template<bool GATHER>
__global__ void __launch_bounds__(512, 1)
gemm_kernel(const int* __restrict__ tokens, const float* __restrict__ A,
            const float* __restrict__ Wm, const float* __restrict__ bias,
            float* __restrict__ C, int K)
{
    __shared__ ull   ATu[16][128];
    __shared__ float Bs[16][128];

    const int tid = threadIdx.x;
    const int r0  = blockIdx.x * 128;
    const int n0  = blockIdx.y * 128;

    const int lrow = tid >> 2;
    const int lkq  = (tid & 3) * 4;
    const float* arow;
    if (GATHER) arow = A + (size_t)tokens[r0 + lrow] * (size_t)K;
    else        arow = A + (size_t)(r0 + lrow) * (size_t)K;

    const int bn = (tid & 31) * 4;
    const int bk = tid >> 5;

    const int ty = tid >> 5;
    const int tx = tid & 31;
    const int cm = ty * 8;
    const int cn = tx * 4;

    ull acc[8][2];
    #pragma unroll
    for (int r = 0; r < 8; r++) { acc[r][0] = 0ull; acc[r][1] = 0ull; }

    #pragma unroll 1
    for (int k0 = 0; k0 < K; k0 += 16) {
        float4 a4 = *(const float4*)(arow + k0 + lkq);
        float4 b4 = *(const float4*)(Wm + (size_t)(k0 + bk) * WIDTH + n0 + bn);
        __syncthreads();
        ATu[lkq + 0][lrow] = pk2(a4.x, a4.x);
        ATu[lkq + 1][lrow] = pk2(a4.y, a4.y);
        ATu[lkq + 2][lrow] = pk2(a4.z, a4.z);
        ATu[lkq + 3][lrow] = pk2(a4.w, a4.w);
        *(float4*)&Bs[bk][bn] = b4;
        __syncthreads();

        #pragma unroll
        for (int kk = 0; kk < 16; kk++) {
            ulonglong2 bv = *(const ulonglong2*)&Bs[kk][cn];
            #pragma unroll
            for (int r = 0; r < 8; r++) {
                ull ad = ATu[kk][cm + r];
                acc[r][0] = ffma2(ad, bv.x, acc[r][0]);
                acc[r][1] = ffma2(ad, bv.y, acc[r][1]);
            }
        }
    }

    const float bv0 = bias[n0 + cn + 0];
    const float bv1 = bias[n0 + cn + 1];
    const float bv2 = bias[n0 + cn + 2];
    const float bv3 = bias[n0 + cn + 3];
    #pragma unroll
    for (int r = 0; r < 8; r++) {
        float c0, c1, c2, c3;
        up2(acc[r][0], c0, c1);
        up2(acc[r][1], c2, c3);
        float4 o = make_float4(c0 + bv0, c1 + bv1, c2 + bv2, c3 + bv3);
        *(float4*)&C[(size_t)(r0 + cm + r) * WIDTH + n0 + cn] = o;
    }
}

// ============================================================================
// RNN scan, cluster-of-2 per batch row.
//  - cluster rank owns output columns [rank*128, rank*128+128)
//  - 256 threads/CTA: column = rank*128 + (tid>>1), k-half = tid&1
//  - each thread holds its 64 U pairs (128 k-values) ENTIRELY in registers
//  - h (256 floats) triple-buffered in smem; halves exchanged via
//    st.shared::cluster + remote mbarrier.arrive.release.cluster
//  - buffer layout: half0 pairs at byte 0..511, half1 at 528..1039 (bank skew)
// ============================================================================
constexpr int HBUF_STRIDE = 1056;       // bytes per h buffer (16B multiple)
constexpr int HALF_OFF    = 528;        // byte offset of half1 pair region

template<bool WRITE_SEQ, bool FINAL>
__global__ void __launch_bounds__(256, 1) __cluster_dims__(2, 1, 1)
rnn_kernel(const float* __restrict__ xw, const float* __restrict__ U,
           float* __restrict__ hs, const float* __restrict__ Wd,
           const float* __restrict__ bd, float* __restrict__ out)
{
    __shared__ __align__(16) unsigned char hraw[3 * HBUF_STRIDE];
    __shared__ __align__(8)  ull mbars[2];
    __shared__ float red[2 * WIDTH];

    const int tid  = threadIdx.x;
    uint32_t rank;
    asm("mov.u32 %0, %%cluster_ctarank;" : "=r"(rank));
    const int b    = blockIdx.x >> 1;
    const int half = tid & 1;
    const int j    = (int)rank * 128 + (tid >> 1);   // output column

    // ---- load this thread's U column-slice into registers (64 f32x2 pairs)
    const int kb = half * 128;
    ull ureg[64];
    #pragma unroll
    for (int m = 0; m < 64; m++)
        ureg[m] = pk2(U[(size_t)(kb + 2 * m) * WIDTH + j],
                      U[(size_t)(kb + 2 * m + 1) * WIDTH + j]);

    // ---- init h buffer 0 to zeros, init mbarriers
    for (int i = tid; i < HBUF_STRIDE; i += 256)
        hraw[i] = 0;
    if (tid == 0) {
        asm volatile("mbarrier.init.shared.b64 [%0], %1;"
                     :: "r"(smem_u32(&mbars[0])), "r"(384) : "memory");
        asm volatile("mbarrier.init.shared.b64 [%0], %1;"
                     :: "r"(smem_u32(&mbars[1])), "r"(384) : "memory");
    }
    __syncthreads();
    // peer mbar init must complete before any remote arrive targets it
    asm volatile("barrier.cluster.arrive.aligned;" ::: "memory");
    asm volatile("barrier.cluster.wait.aligned;" ::: "memory");

    const uint32_t hraw_u32 = smem_u32(hraw);
    const uint32_t mbar_u32 = smem_u32(mbars);
    uint32_t peer_hraw, peer_mbar;
    {
        uint32_t pr = rank ^ 1u;
        asm("mapa.shared::cluster.u32 %0, %1, %2;" : "=r"(peer_hraw) : "r"(hraw_u32), "r"(pr));
        asm("mapa.shared::cluster.u32 %0, %1, %2;" : "=r"(peer_mbar) : "r"(mbar_u32), "r"(pr));
    }

    // byte offset of h[j] inside a buffer
    const uint32_t wroff = (uint32_t)((j >= 128 ? HALF_OFF : 0)
                                      + ((j & 127) >> 1) * 8 + (j & 1) * 4);

    const float* xb = xw + (size_t)b * SEQ * WIDTH + j;
    float xt_next = xb[0];

    int rd = 0, wr = 1;   // buffer indices (mod 3 rotation)

    #pragma unroll 1
    for (int t = 0; t < SEQ; t++) {
        const float xt = xt_next;
        if (t + 1 < SEQ) xt_next = xb[(size_t)(t + 1) * WIDTH];

        const ull* hp = (const ull*)(hraw + rd * HBUF_STRIDE + half * HALF_OFF);
        ull a0 = 0ull, a1 = 0ull, a2 = 0ull, a3 = 0ull;
        #pragma unroll
        for (int m = 0; m < 64; m += 4) {
            ulonglong2 h01 = *(const ulonglong2*)(hp + m);
            ulonglong2 h23 = *(const ulonglong2*)(hp + m + 2);
            a0 = ffma2(h01.x, ureg[m + 0], a0);
            a1 = ffma2(h01.y, ureg[m + 1], a1);
            a2 = ffma2(h23.x, ureg[m + 2], a2);
            a3 = ffma2(h23.y, ureg[m + 3], a3);
        }
        float s0, s1, s2, s3, s4, s5, s6, s7;
        up2(a0, s0, s1); up2(a1, s2, s3); up2(a2, s4, s5); up2(a3, s6, s7);
        float s = (((s0 + s1) + (s2 + s3)) + ((s4 + s5) + (s6 + s7)));
        // combine the two k-halves (lane pair 2k / 2k+1)
        s += __shfl_xor_sync(0xFFFFFFFFu, s, 1);
        const float hn = tanhf(xt + s);

        const uint32_t mb_l = mbar_u32 + (uint32_t)((t & 1) * 8);
        const uint32_t mb_r = peer_mbar + (uint32_t)((t & 1) * 8);

        if (half == 0) {
            // local write
            *(float*)(hraw + wr * HBUF_STRIDE + wroff) = hn;
            // remote write + remote arrive (release at cluster scope)
            uint32_t raddr = peer_hraw + (uint32_t)(wr * HBUF_STRIDE) + wroff;
            asm volatile("st.shared::cluster.f32 [%0], %1;"
                         :: "r"(raddr), "f"(hn) : "memory");
            asm volatile("mbarrier.arrive.release.cluster.shared::cluster.b64 _, [%0];"
                         :: "r"(mb_r) : "memory");
            if (WRITE_SEQ)
                hs[(size_t)b * SEQ * WIDTH + (size_t)t * WIDTH + j] = hn;
        }
        // local arrive (release.cta default: publishes local h write)
        asm volatile("mbarrier.arrive.shared.b64 _, [%0];" :: "r"(mb_l) : "memory");

        // wait: 256 local arrives + 128 remote arrives
        {
            const uint32_t parity = (uint32_t)((t >> 1) & 1);
            uint32_t done;
            asm volatile(
                "{\n\t.reg .pred p;\n\t"
                "mbarrier.try_wait.parity.acquire.cluster.shared::cta.b64 p, [%1], %2;\n\t"
                "selp.b32 %0, 1, 0, p;\n\t}"
                : "=r"(done) : "r"(mb_l), "r"(parity) : "memory");
            if (!done) {
                asm volatile(
                    "{\n\t.reg .pred P1;\n\t"
                    "WL_%=:\n\t"
                    "mbarrier.try_wait.parity.acquire.cluster.shared::cta.b64 P1, [%0], %1, 0x989680;\n\t"
                    "@P1 bra.uni WD_%=;\n\t"
                    "bra.uni WL_%=;\n\t"
                    "WD_%=:\n\t}"
                    :: "r"(mb_l), "r"(parity) : "memory");
            }
        }

        rd = wr;
        wr = (wr == 2) ? 0 : wr + 1;
    }

    if (FINAL && rank == 0) {
        // full final h lives in hraw[rd] (both halves, exchange complete)
        const float h = *(const float*)(hraw + rd * HBUF_STRIDE
                                        + (tid >= 128 ? HALF_OFF : 0)
                                        + ((tid & 127) >> 1) * 8 + (tid & 1) * 4);
        red[tid]         = h * Wd[tid * 2 + 0];
        red[WIDTH + tid] = h * Wd[tid * 2 + 1];
        __syncthreads();
        #pragma unroll
        for (int sft = 128; sft > 0; sft >>= 1) {
            if (tid < sft) {
                red[tid]         += red[tid + sft];
                red[WIDTH + tid] += red[WIDTH + tid + sft];
            }
            __syncthreads();
        }
        if (tid == 0) {
            const float l0 = red[0] + bd[0];
            const float l1 = red[WIDTH] + bd[1];
            const float mx = fmaxf(l0, l1);
            const float e0 = expf(l0 - mx);
            const float e1 = expf(l1 - mx);
            const float inv = 1.0f / (e0 + e1);
            out[b * 2 + 0] = e0 * inv;
            out[b * 2 + 1] = e1 * inv;
        }
    }

    // no CTA may exit while peer stores/arrives into its smem may be in flight
    asm volatile("barrier.cluster.arrive.aligned;" ::: "memory");
    asm volatile("barrier.cluster.wait.aligned;" ::: "memory");
}

// ============================================================================
// launcher
// ============================================================================
extern "C" void kernel_launch(void* const* d_in, const int* in_sizes, int n_in,
                              void* d_out, int out_size)
{
    const int*   tokens = (const int*)  d_in[0];
    const float* emb    = (const float*)d_in[1];
    const float* W1     = (const float*)d_in[2];
    const float* U1     = (const float*)d_in[3];
    const float* b1     = (const float*)d_in[4];
    const float* W2     = (const float*)d_in[5];
    const float* U2     = (const float*)d_in[6];
    const float* b2     = (const float*)d_in[7];
    const float* Wd     = (const float*)d_in[8];
    const float* bd     = (const float*)d_in[9];
    float* out = (float*)d_out;

    float* bufA; cudaGetSymbolAddress((void**)&bufA, g_bufA);
    float* bufB; cudaGetSymbolAddress((void**)&bufB, g_bufB);

    dim3 ggrid(ROWS / 128, WIDTH / 128);   // (256, 2)

    // 1) xw1 = emb[tokens] @ W1 + b1  -> bufA
    gemm_kernel<true><<<ggrid, 512>>>(tokens, emb, W1, b1, bufA, EMBED);

    // 2) RNN1 scan (cluster-2 per row) -> h1 sequence in bufB
    rnn_kernel<true, false><<<2 * BATCH, 256>>>(bufA, U1, bufB,
                                                nullptr, nullptr, nullptr);

    // 3) xw2 = h1 @ W2 + b2 -> bufA
    gemm_kernel<false><<<ggrid, 512>>>(nullptr, bufB, W2, b2, bufA, WIDTH);

    // 4) RNN2 scan, fused dense + softmax -> out
    rnn_kernel<false, true><<<2 * BATCH, 256>>>(bufA, U2, nullptr,
                                                Wd, bd, out);

    (void)in_sizes; (void)n_in; (void)out_size;
}